// round 2
// baseline (speedup 1.0000x reference)
#include <cuda_runtime.h>

#define NB 16
#define NL 576
#define NH 12
#define ND 64
#define NM 8
#define NUM_STAB 1e-3f
#define RATIO 0.3535533905932738f   // 1/sqrt(8)

typedef unsigned long long ull;

// ---------------- device scratch ----------------
__device__ float g_qp[NB * NH * NL * NM];   // q' features [B,H,L,M]
__device__ float g_kp[NB * NH * NL * NM];   // k' features [B,H,L,M]
__device__ float g_mcolp[NH * 4 * NL];      // partial column sums of mask
__device__ float g_ks[NB * NH * NM];        // ks_sum [B,H,M]

// ---------------- packed f32x2 helpers ----------------
__device__ __forceinline__ ull pk2(float lo, float hi) {
    ull r;
    asm("mov.b64 %0, {%1, %2};" : "=l"(r)
        : "r"(__float_as_uint(lo)), "r"(__float_as_uint(hi)));
    return r;
}
__device__ __forceinline__ void fma2(ull& d, ull a, ull b) {
    asm("fma.rn.f32x2 %0, %1, %2, %0;" : "+l"(d) : "l"(a), "l"(b));
}
__device__ __forceinline__ ull mul2(ull a, ull b) {
    ull r;
    asm("mul.rn.f32x2 %0, %1, %2;" : "=l"(r) : "l"(a), "l"(b));
    return r;
}
__device__ __forceinline__ void upk2(ull v, float& lo, float& hi) {
    unsigned int l, h;
    asm("mov.b64 {%0, %1}, %2;" : "=r"(l), "=r"(h) : "l"(v));
    lo = __uint_as_float(l);
    hi = __uint_as_float(h);
}

// ---------------- kernel 1: ReLU features (output [B,H,L,M]) ----------------
__global__ void feat_kernel(const float* __restrict__ qin,
                            const float* __restrict__ kin,
                            const float* __restrict__ proj) {
    const float* x = blockIdx.y ? kin : qin;
    float* o = blockIdx.y ? g_kp : g_qp;

    __shared__ __align__(16) float sx[32][68];
    __shared__ float spt[64][8];

    int tid = threadIdx.x;
    int row0 = blockIdx.x * 32;

    for (int i = tid; i < 512; i += 128) {
        int mm = i >> 6, cc = i & 63;
        spt[cc][mm] = proj[i];
    }
    for (int i = tid; i < 512; i += 128) {
        int r = i >> 4, c4 = i & 15;
        *(float4*)&sx[r][c4 * 4] =
            ((const float4*)x)[(size_t)(row0 + r) * 16 + c4];
    }
    __syncthreads();

    int r = tid >> 2;
    int m2 = tid & 3;
    ull acc = 0ull;
#pragma unroll
    for (int c = 0; c < 64; c++) {
        float a = sx[r][c];
        float2 bv = *(const float2*)&spt[c][m2 * 2];
        fma2(acc, pk2(a, a), pk2(bv.x, bv.y));
    }
    float s0, s1;
    upk2(acc, s0, s1);
    s0 = fmaxf(s0 * RATIO, 0.0f) + NUM_STAB;
    s1 = fmaxf(s1 * RATIO, 0.0f) + NUM_STAB;

    int row = row0 + r;                    // linear over [B,L,H]
    int b = row / (NL * NH);
    int rem = row - b * (NL * NH);
    int l = rem / NH;
    int h = rem - l * NH;
    float2 res = make_float2(s0, s1);
    *(float2*)(o + (((size_t)b * NH + h) * NL + l) * NM + m2 * 2) = res;
}

// ---------------- kernel 2: mask column partial sums ----------------
__global__ void mcol_kernel(const float* __restrict__ mask) {
    int h = blockIdx.x;
    int q = blockIdx.y;
    int j = threadIdx.x;
    const float* mh = mask + (size_t)h * NL * NL;
    int i0 = q * (NL / 4);
    float s0 = 0.f, s1 = 0.f, s2 = 0.f, s3 = 0.f;
#pragma unroll 4
    for (int i = 0; i < NL / 4; i += 4) {
        s0 += mh[(size_t)(i0 + i + 0) * NL + j];
        s1 += mh[(size_t)(i0 + i + 1) * NL + j];
        s2 += mh[(size_t)(i0 + i + 2) * NL + j];
        s3 += mh[(size_t)(i0 + i + 3) * NL + j];
    }
    g_mcolp[(h * 4 + q) * NL + j] = (s0 + s1) + (s2 + s3);
}

// ---------------- kernel 3: ks_sum ----------------
__global__ void ks_kernel() {
    int bh = blockIdx.x;           // b*NH + h — matches [B,H,L,M] layout
    int h = bh % NH;
    int tid = threadIdx.x;
    int m = tid & 7;
    int js = tid >> 3;
    float s = 0.f;
    for (int j = js; j < NL; j += 32) {
        float mc = g_mcolp[(h * 4 + 0) * NL + j] + g_mcolp[(h * 4 + 1) * NL + j]
                 + g_mcolp[(h * 4 + 2) * NL + j] + g_mcolp[(h * 4 + 3) * NL + j];
        s += mc * g_kp[((size_t)bh * NL + j) * NM + m];
    }
    __shared__ float red[256];
    red[tid] = s;
    __syncthreads();
    for (int off = 128; off >= 8; off >>= 1) {
        if (tid < off) red[tid] += red[tid + off];
        __syncthreads();
    }
    if (tid < 8) g_ks[bh * NM + tid] = red[tid];
}

// ---------------- kernel 4: main masked-attention ----------------
// grid (5, 192), block 128. Ti=128 (tail 64), Tj=32. Thread tile 8x8.
__global__ void __launch_bounds__(128)
attn_kernel(const float* __restrict__ value,
            const float* __restrict__ mask,
            float* __restrict__ out) {
    int i0 = blockIdx.x * 128;
    int bh = blockIdx.y;
    int b = bh / NH, h = bh % NH;
    int rows = NL - i0; if (rows > 128) rows = 128;
    int tid = threadIdx.x;

    __shared__ __align__(16) float sq[128][8];
    __shared__ __align__(16) float sk[32][8];
    __shared__ float smk[128][33];                 // mask tile [i][j]
    __shared__ __align__(16) float ss[32][132];    // S^T [j][i]
    __shared__ __align__(16) float sv[32][68];     // V tile [j][d]
    __shared__ float sks[8];

    // stage q' tile ([B,H,L,M] → contiguous) + ks
    {
        int r = tid >> 1, half = tid & 1;
        const float* qbase = g_qp + ((size_t)bh * NL + i0) * NM;
        if (r < rows)
            *(float4*)&sq[r][half * 4] = *(const float4*)(qbase + r * NM + half * 4);
        if (r + 64 < rows)
            *(float4*)&sq[r + 64][half * 4] = *(const float4*)(qbase + (r + 64) * NM + half * 4);
    }
    if (tid < 8) sks[tid] = g_ks[bh * NM + tid];
    __syncthreads();

    // per-thread phase-A q' row (row = tid), packed
    float4 q0 = *(const float4*)&sq[tid][0];
    float4 q1 = *(const float4*)&sq[tid][4];
    ull qa = pk2(q0.x, q0.y), qb = pk2(q0.z, q0.w);
    ull qc = pk2(q1.x, q1.y), qd = pk2(q1.z, q1.w);

    const float* maskh = mask + (size_t)h * NL * NL;
    const float* kbase = g_kp + (size_t)bh * NL * NM;

    int ty = tid >> 3;   // 0..15 → rows ty*8..+7
    int tx = tid & 7;    // 0..7  → cols tx*8..+7
    ull acc[8][4];
#pragma unroll
    for (int r = 0; r < 8; r++) {
        acc[r][0] = 0ull; acc[r][1] = 0ull; acc[r][2] = 0ull; acc[r][3] = 0ull;
    }

    for (int j0 = 0; j0 < NL; j0 += 32) {
        __syncthreads();   // previous phase B done with ss/sv

        // stage k' tile (32x8)
        if (tid < 64) {
            int jr = tid >> 1, half = tid & 1;
            *(float4*)&sk[jr][half * 4] =
                *(const float4*)(kbase + (size_t)(j0 + jr) * NM + half * 4);
        }
        // stage V tile (32x64) as float2, warp-per-row → conflict-free
        {
            int c2 = tid & 31, rr = tid >> 5;    // rr 0..3
            const float* vbase = value + (((size_t)b * NL + j0) * NH + h) * ND;
#pragma unroll
            for (int s = 0; s < 8; s++) {
                int jr = rr + s * 4;
                *(float2*)&sv[jr][c2 * 2] =
                    *(const float2*)(vbase + (size_t)jr * NH * ND + c2 * 2);
            }
        }
        // stage mask tile (128x32): coalesced LDG.128, scalar conflict-free STS
        {
            int c4 = tid & 7, r8 = tid >> 3;     // r8 0..15
#pragma unroll
            for (int s = 0; s < 8; s++) {
                int r = r8 + s * 16;
                if (i0 + r < NL) {
                    float4 mv = *(const float4*)(maskh + (size_t)(i0 + r) * NL + j0 + c4 * 4);
                    smk[r][c4 * 4 + 0] = mv.x;
                    smk[r][c4 * 4 + 1] = mv.y;
                    smk[r][c4 * 4 + 2] = mv.z;
                    smk[r][c4 * 4 + 3] = mv.w;
                }
            }
        }
        __syncthreads();

        // phase A: thread owns row i=tid; S^T[j][i] = (q'.k')*mask
#pragma unroll 4
        for (int j = 0; j < 32; j++) {
            float4 k0 = *(const float4*)&sk[j][0];
            float4 k1 = *(const float4*)&sk[j][4];
            ull d = mul2(qa, pk2(k0.x, k0.y));
            fma2(d, qb, pk2(k0.z, k0.w));
            fma2(d, qc, pk2(k1.x, k1.y));
            fma2(d, qd, pk2(k1.z, k1.w));
            float lo, hi;
            upk2(d, lo, hi);
            ss[j][tid] = (lo + hi) * smk[tid][j];
        }
        __syncthreads();

        // phase B: acc[128x64] += S[128x32] @ V[32x64], 8x8 per thread
        const float4* ssr = (const float4*)ss;
        const float4* svr = (const float4*)sv;
#pragma unroll 4
        for (int kk = 0; kk < 32; kk++) {
            float4 a0 = ssr[kk * 33 + ty * 2];
            float4 a1 = ssr[kk * 33 + ty * 2 + 1];
            float4 v0 = svr[kk * 17 + tx * 2];
            float4 v1 = svr[kk * 17 + tx * 2 + 1];
            ull vp0 = pk2(v0.x, v0.y), vp1 = pk2(v0.z, v0.w);
            ull vp2 = pk2(v1.x, v1.y), vp3 = pk2(v1.z, v1.w);
            ull a;
#define ROWFMA(r, av) \
            a = pk2(av, av); \
            fma2(acc[r][0], a, vp0); fma2(acc[r][1], a, vp1); \
            fma2(acc[r][2], a, vp2); fma2(acc[r][3], a, vp3);
            ROWFMA(0, a0.x) ROWFMA(1, a0.y) ROWFMA(2, a0.z) ROWFMA(3, a0.w)
            ROWFMA(4, a1.x) ROWFMA(5, a1.y) ROWFMA(6, a1.z) ROWFMA(7, a1.w)
#undef ROWFMA
        }
    }

    // epilogue: divide by normalizer = q'_i . ks_sum, write
    float* obase = out + (((size_t)b * NL + i0) * NH + h) * ND;
#pragma unroll
    for (int r = 0; r < 8; r++) {
        int i = ty * 8 + r;
        if (i < rows) {
            float nrm = sq[i][0] * sks[0] + sq[i][1] * sks[1]
                      + sq[i][2] * sks[2] + sq[i][3] * sks[3]
                      + sq[i][4] * sks[4] + sq[i][5] * sks[5]
                      + sq[i][6] * sks[6] + sq[i][7] * sks[7];
            float inv = 1.0f / nrm;
            float o0, o1, o2, o3, o4, o5, o6, o7;
            upk2(acc[r][0], o0, o1);
            upk2(acc[r][1], o2, o3);
            upk2(acc[r][2], o4, o5);
            upk2(acc[r][3], o6, o7);
            float4 w0 = make_float4(o0 * inv, o1 * inv, o2 * inv, o3 * inv);
            float4 w1 = make_float4(o4 * inv, o5 * inv, o6 * inv, o7 * inv);
            *(float4*)(obase + (size_t)i * NH * ND + tx * 8)     = w0;
            *(float4*)(obase + (size_t)i * NH * ND + tx * 8 + 4) = w1;
        }
    }
}

// ---------------- launch ----------------
extern "C" void kernel_launch(void* const* d_in, const int* in_sizes, int n_in,
                              void* d_out, int out_size) {
    const float* q    = (const float*)d_in[0];
    const float* k    = (const float*)d_in[1];
    const float* v    = (const float*)d_in[2];
    const float* proj = (const float*)d_in[3];
    const float* mask = (const float*)d_in[4];
    float* out = (float*)d_out;

    feat_kernel<<<dim3((NB * NL * NH) / 32, 2), 128>>>(q, k, proj);
    mcol_kernel<<<dim3(NH, 4), NL>>>(mask);
    ks_kernel<<<NB * NH, 256>>>();
    attn_kernel<<<dim3(5, NB * NH), 128>>>(v, mask, out);
}

// round 3
// speedup vs baseline: 1.8609x; 1.8609x over previous
#include <cuda_runtime.h>

#define NB 16
#define NL 576
#define NH 12
#define ND 64
#define NM 8
#define NUM_STAB 1e-3f
#define RATIO 0.3535533905932738f   // 1/sqrt(8)

typedef unsigned long long ull;

// ---------------- device scratch ----------------
__device__ float g_qp[NB * NH * NL * NM];   // q' features [B,H,L,M]
__device__ float g_kp[NB * NH * NL * NM];   // k' features [B,H,L,M]
__device__ float g_mcolp[NH * 4 * NL];      // partial column sums of mask
__device__ float g_ks[NB * NH * NM];        // ks_sum [B,H,M]

// ---------------- packed f32x2 helpers ----------------
__device__ __forceinline__ ull pk2(float lo, float hi) {
    ull r;
    asm("mov.b64 %0, {%1, %2};" : "=l"(r)
        : "r"(__float_as_uint(lo)), "r"(__float_as_uint(hi)));
    return r;
}
__device__ __forceinline__ void fma2(ull& d, ull a, ull b) {
    asm("fma.rn.f32x2 %0, %1, %2, %0;" : "+l"(d) : "l"(a), "l"(b));
}
__device__ __forceinline__ ull mul2(ull a, ull b) {
    ull r;
    asm("mul.rn.f32x2 %0, %1, %2;" : "=l"(r) : "l"(a), "l"(b));
    return r;
}
__device__ __forceinline__ void upk2(ull v, float& lo, float& hi) {
    unsigned int l, h;
    asm("mov.b64 {%0, %1}, %2;" : "=r"(l), "=r"(h) : "l"(v));
    lo = __uint_as_float(l);
    hi = __uint_as_float(h);
}

// ---------------- kernel 1: ReLU features (output [B,H,L,M]) ----------------
__global__ void feat_kernel(const float* __restrict__ qin,
                            const float* __restrict__ kin,
                            const float* __restrict__ proj) {
    const float* x = blockIdx.y ? kin : qin;
    float* o = blockIdx.y ? g_kp : g_qp;

    __shared__ __align__(16) float sx[32][68];
    __shared__ float spt[64][8];

    int tid = threadIdx.x;
    int row0 = blockIdx.x * 32;

    for (int i = tid; i < 512; i += 128) {
        int mm = i >> 6, cc = i & 63;
        spt[cc][mm] = proj[i];
    }
    for (int i = tid; i < 512; i += 128) {
        int r = i >> 4, c4 = i & 15;
        *(float4*)&sx[r][c4 * 4] =
            ((const float4*)x)[(size_t)(row0 + r) * 16 + c4];
    }
    __syncthreads();

    int r = tid >> 2;
    int m2 = tid & 3;
    ull acc = 0ull;
#pragma unroll
    for (int c = 0; c < 64; c++) {
        float a = sx[r][c];
        float2 bv = *(const float2*)&spt[c][m2 * 2];
        fma2(acc, pk2(a, a), pk2(bv.x, bv.y));
    }
    float s0, s1;
    upk2(acc, s0, s1);
    s0 = fmaxf(s0 * RATIO, 0.0f) + NUM_STAB;
    s1 = fmaxf(s1 * RATIO, 0.0f) + NUM_STAB;

    int row = row0 + r;                    // linear over [B,L,H]
    int b = row / (NL * NH);
    int rem = row - b * (NL * NH);
    int l = rem / NH;
    int h = rem - l * NH;
    float2 res = make_float2(s0, s1);
    *(float2*)(o + (((size_t)b * NH + h) * NL + l) * NM + m2 * 2) = res;
}

// ---------------- kernel 2: mask column partial sums ----------------
__global__ void mcol_kernel(const float* __restrict__ mask) {
    int h = blockIdx.x;
    int q = blockIdx.y;
    int j = threadIdx.x;
    const float* mh = mask + (size_t)h * NL * NL;
    int i0 = q * (NL / 4);
    float s0 = 0.f, s1 = 0.f, s2 = 0.f, s3 = 0.f;
#pragma unroll 4
    for (int i = 0; i < NL / 4; i += 4) {
        s0 += mh[(size_t)(i0 + i + 0) * NL + j];
        s1 += mh[(size_t)(i0 + i + 1) * NL + j];
        s2 += mh[(size_t)(i0 + i + 2) * NL + j];
        s3 += mh[(size_t)(i0 + i + 3) * NL + j];
    }
    g_mcolp[(h * 4 + q) * NL + j] = (s0 + s1) + (s2 + s3);
}

// ---------------- kernel 3: ks_sum ----------------
__global__ void ks_kernel() {
    int bh = blockIdx.x;
    int h = bh % NH;
    int tid = threadIdx.x;
    int m = tid & 7;
    int js = tid >> 3;
    float s = 0.f;
    for (int j = js; j < NL; j += 32) {
        float mc = g_mcolp[(h * 4 + 0) * NL + j] + g_mcolp[(h * 4 + 1) * NL + j]
                 + g_mcolp[(h * 4 + 2) * NL + j] + g_mcolp[(h * 4 + 3) * NL + j];
        s += mc * g_kp[((size_t)bh * NL + j) * NM + m];
    }
    __shared__ float red[256];
    red[tid] = s;
    __syncthreads();
    for (int off = 128; off >= 8; off >>= 1) {
        if (tid < off) red[tid] += red[tid + off];
        __syncthreads();
    }
    if (tid < 8) g_ks[bh * NM + tid] = red[tid];
}

// ---------------- kernel 4: main masked-attention ----------------
// grid (9, 192), block 128. Ti=64, Tj=32, thread tile 8x4 (R1 skeleton).
__global__ void __launch_bounds__(128)
attn_kernel(const float* __restrict__ value,
            const float* __restrict__ mask,
            float* __restrict__ out) {
    int i0 = blockIdx.x * 64;
    int bh = blockIdx.y;
    int b = bh / NH, h = bh % NH;
    int tid = threadIdx.x;

    __shared__ __align__(16) float sk[32][12];     // k' tile (stride 12: f4-aligned)
    __shared__ float smkT[32][65];                 // mask tile transposed [j][i]
    __shared__ __align__(16) float ss[32][68];     // S^T [j][i]
    __shared__ __align__(16) float sv[32][68];     // V tile [j][d]
    __shared__ float snrm[64];
    __shared__ float sks[8];

    // ---- per-thread q' row (phase A): i = tid & 63 ----
    int ia = tid & 63;
    int jg = tid >> 6;       // 0 or 1 -> j range jg*16 .. jg*16+15
    const float* qrow = g_qp + ((size_t)bh * NL + i0 + ia) * NM;
    float4 qf0 = *(const float4*)qrow;
    float4 qf1 = *(const float4*)(qrow + 4);
    ull qa = pk2(qf0.x, qf0.y), qb = pk2(qf0.z, qf0.w);
    ull qc = pk2(qf1.x, qf1.y), qd = pk2(qf1.z, qf1.w);

    if (tid < 8) sks[tid] = g_ks[bh * NM + tid];
    __syncthreads();

    // normalizer for row ia (computed by jg==0 threads only)
    if (jg == 0) {
        snrm[ia] = qf0.x * sks[0] + qf0.y * sks[1] + qf0.z * sks[2] + qf0.w * sks[3]
                 + qf1.x * sks[4] + qf1.y * sks[5] + qf1.z * sks[6] + qf1.w * sks[7];
    }

    const float* maskh = mask + (size_t)h * NL * NL;
    const float* kbase = g_kp + (size_t)bh * NL * NM;
    const float* vbase0 = value + (((size_t)b * NL) * NH + h) * ND;

    int ty = tid >> 4;   // 0..7  -> rows ty*8..+7
    int tx = tid & 15;   // 0..15 -> cols tx*4..+3
    ull acc[8][2];
#pragma unroll
    for (int r = 0; r < 8; r++) { acc[r][0] = 0ull; acc[r][1] = 0ull; }

    for (int j0 = 0; j0 < NL; j0 += 32) {
        __syncthreads();   // prev phase B done with ss/sv; phase A done with sk/smkT

        // stage k' tile (32x8) into sk (stride 12)
        if (tid < 64) {
            int jr = tid >> 1, half = tid & 1;
            *(float4*)&sk[jr][half * 4] =
                *(const float4*)(kbase + (size_t)(j0 + jr) * NM + half * 4);
        }
        // stage V tile (32x64): float4 per thread, 4 iters
        {
            int c4 = (tid & 15) * 4, jr0 = tid >> 4;   // jr0 0..7
            const float* vb = vbase0 + (size_t)j0 * NH * ND;
#pragma unroll
            for (int s = 0; s < 4; s++) {
                int jr = jr0 + s * 8;
                *(float4*)&sv[jr][c4] =
                    *(const float4*)(vb + (size_t)jr * NH * ND + c4);
            }
        }
        // stage mask tile transposed: smkT[j][i] = mask[i0+i][j0+j]
        {
            int c4 = tid & 7, r0 = tid >> 3;    // r0 0..15
#pragma unroll
            for (int s = 0; s < 4; s++) {
                int r = r0 + s * 16;
                float4 mv = *(const float4*)(maskh + (size_t)(i0 + r) * NL + j0 + c4 * 4);
                smkT[c4 * 4 + 0][r] = mv.x;
                smkT[c4 * 4 + 1][r] = mv.y;
                smkT[c4 * 4 + 2][r] = mv.z;
                smkT[c4 * 4 + 3][r] = mv.w;
            }
        }
        __syncthreads();

        // phase A: thread (ia, jg) computes S^T[j][ia] for its 16 j's
#pragma unroll
        for (int jj = 0; jj < 16; jj++) {
            int j = jg * 16 + jj;
            ulonglong2 K0 = *(const ulonglong2*)&sk[j][0];
            ulonglong2 K1 = *(const ulonglong2*)&sk[j][4];
            ull d = mul2(qa, K0.x);
            fma2(d, qb, K0.y);
            fma2(d, qc, K1.x);
            fma2(d, qd, K1.y);
            float lo, hi;
            upk2(d, lo, hi);
            ss[j][ia] = (lo + hi) * smkT[j][ia];
        }
        __syncthreads();

        // phase B: acc[64x64] += S[64x32] @ V[32x64], 8x4 per thread
#pragma unroll 8
        for (int kk = 0; kk < 32; kk++) {
            float4 a0 = *(const float4*)&ss[kk][ty * 8];
            float4 a1 = *(const float4*)&ss[kk][ty * 8 + 4];
            ulonglong2 V2 = *(const ulonglong2*)&sv[kk][tx * 4];
            ull vp0 = V2.x, vp1 = V2.y;
            ull a;
#define ROWFMA(r, av) \
            a = pk2(av, av); \
            fma2(acc[r][0], a, vp0); fma2(acc[r][1], a, vp1);
            ROWFMA(0, a0.x) ROWFMA(1, a0.y) ROWFMA(2, a0.z) ROWFMA(3, a0.w)
            ROWFMA(4, a1.x) ROWFMA(5, a1.y) ROWFMA(6, a1.z) ROWFMA(7, a1.w)
#undef ROWFMA
        }
    }

    // epilogue
    float* obase = out + (((size_t)b * NL + i0) * NH + h) * ND;
#pragma unroll
    for (int r = 0; r < 8; r++) {
        int i = ty * 8 + r;
        float inv = 1.0f / snrm[i];
        float o0, o1, o2, o3;
        upk2(acc[r][0], o0, o1);
        upk2(acc[r][1], o2, o3);
        float4 w = make_float4(o0 * inv, o1 * inv, o2 * inv, o3 * inv);
        *(float4*)(obase + (size_t)i * NH * ND + tx * 4) = w;
    }
}

// ---------------- launch ----------------
extern "C" void kernel_launch(void* const* d_in, const int* in_sizes, int n_in,
                              void* d_out, int out_size) {
    const float* q    = (const float*)d_in[0];
    const float* k    = (const float*)d_in[1];
    const float* v    = (const float*)d_in[2];
    const float* proj = (const float*)d_in[3];
    const float* mask = (const float*)d_in[4];
    float* out = (float*)d_out;

    feat_kernel<<<dim3((NB * NL * NH) / 32, 2), 128>>>(q, k, proj);
    mcol_kernel<<<dim3(NH, 4), NL>>>(mask);
    ks_kernel<<<NB * NH, 256>>>();
    attn_kernel<<<dim3(NL / 64, NB * NH), 128>>>(v, mask, out);
}